// round 1
// baseline (speedup 1.0000x reference)
#include <cuda_runtime.h>
#include <cuda_bf16.h>
#include <math.h>

// ---------------------------------------------------------------------------
// Problem constants
// ---------------------------------------------------------------------------
#define B_    4
#define S_    1020
#define D_    1024
#define H_    16
#define L_    4
#define DH_   64
#define TPB_  17
#define BS_   (B_ * S_)        // 4080 rows
#define VOBS_ 4096
#define VACT_ 16
#define D4_   4096
#define NOBS_ 960              // obs-head rows per batch
#define NACT_ 60               // act rows per batch
#define EPS_  1e-3f

// ---------------------------------------------------------------------------
// Scratch (static __device__ arrays -- no runtime allocation allowed)
// ---------------------------------------------------------------------------
__device__ float g_x  [BS_ * D_];
__device__ float g_h  [BS_ * D_];
__device__ float g_q  [BS_ * D_];
__device__ float g_k  [BS_ * D_];
__device__ float g_v  [BS_ * D_];
__device__ float g_o  [BS_ * D_];
__device__ float g_mlp[BS_ * D4_];
__device__ float g_xo [B_ * NOBS_ * D_];
__device__ float g_t1 [B_ * NOBS_ * D_];
__device__ float g_xe [B_ * NACT_ * D_];
__device__ float g_t2 [B_ * NACT_ * D_];

// ---------------------------------------------------------------------------
// Embedding: x[b,s,:] = (obs? emb_obs[tok] : emb_act[tok]) + pos_emb[s]
// grid = BS_, block = 256 (each thread one float4 of the 1024-wide row)
// ---------------------------------------------------------------------------
__global__ __launch_bounds__(256) void embed_kernel(
    const int* __restrict__ tok, const float* __restrict__ pos_emb,
    const float* __restrict__ eobs, const float* __restrict__ eact,
    float* __restrict__ X)
{
    int row = blockIdx.x;
    int b = row / S_;
    int s = row - b * S_;
    int t = threadIdx.x;
    int tk = tok[row];
    bool obs = (s % TPB_) < (TPB_ - 1);
    const float4* e = (const float4*)(obs ? (eobs + (size_t)min(tk, VOBS_ - 1) * D_)
                                          : (eact + (size_t)min(tk, VACT_ - 1) * D_));
    const float4* p = (const float4*)(pos_emb + (size_t)s * D_);
    float4 a = e[t], c = p[t];
    ((float4*)(X + (size_t)row * D_))[t] =
        make_float4(a.x + c.x, a.y + c.y, a.z + c.z, a.w + c.w);
}

// ---------------------------------------------------------------------------
// LayerNorm over last dim (1024). grid = rows, block = 256.
// ---------------------------------------------------------------------------
__global__ __launch_bounds__(256) void ln_kernel(
    const float* __restrict__ X, const float* __restrict__ g,
    const float* __restrict__ bb, float* __restrict__ Y)
{
    int row = blockIdx.x;
    int t = threadIdx.x;
    const float4* xp = (const float4*)(X + (size_t)row * D_);
    float4 v = xp[t];
    float s  = v.x + v.y + v.z + v.w;
    float ss = v.x * v.x + v.y * v.y + v.z * v.z + v.w * v.w;
#pragma unroll
    for (int off = 16; off > 0; off >>= 1) {
        s  += __shfl_xor_sync(0xffffffffu, s,  off);
        ss += __shfl_xor_sync(0xffffffffu, ss, off);
    }
    __shared__ float smA[8], smB[8];
    int lane = t & 31, wid = t >> 5;
    if (lane == 0) { smA[wid] = s; smB[wid] = ss; }
    __syncthreads();
    float tot = 0.f, tot2 = 0.f;
#pragma unroll
    for (int i = 0; i < 8; i++) { tot += smA[i]; tot2 += smB[i]; }
    float mean = tot * (1.f / D_);
    float var  = tot2 * (1.f / D_) - mean * mean;
    float rstd = rsqrtf(var + EPS_);
    const float4* gp = (const float4*)g;
    const float4* bp = (const float4*)bb;
    float4 gv = gp[t], bv = bp[t];
    float4 o;
    o.x = (v.x - mean) * rstd * gv.x + bv.x;
    o.y = (v.y - mean) * rstd * gv.y + bv.y;
    o.z = (v.z - mean) * rstd * gv.z + bv.z;
    o.w = (v.w - mean) * rstd * gv.w + bv.w;
    ((float4*)(Y + (size_t)row * D_))[t] = o;
}

// ---------------------------------------------------------------------------
// SGEMM: C = act(A[MxK] @ W[KxN] + bias) (+ R residual)
// 128x128 tile, BK=16, 256 threads, 8x8 microtile, smem double-buffered.
// ACT: 0=none, 1=gelu(exact), 2=relu
// ---------------------------------------------------------------------------
#define BM 128
#define BN 128
#define BKK 16

template <int ACT, bool RES>
__global__ __launch_bounds__(256, 2) void sgemm_kernel(
    const float* __restrict__ A, const float* __restrict__ W,
    const float* __restrict__ bias, const float* __restrict__ Rp,
    float* __restrict__ C, int M, int N, int K)
{
    __shared__ float As[2][BKK][BM + 4];
    __shared__ float Bs[2][BKK][BN];
    const int t  = threadIdx.x;
    const int tx = t & 15, ty = t >> 4;
    const int mb = blockIdx.y * BM, nb = blockIdx.x * BN;
    const int ra = t >> 2,  ca = (t & 3) * 4;   // A tile: rows ra, ra+64; cols ca..ca+3
    const int rb = t >> 5,  cb = (t & 31) * 4;  // B tile: rows rb, rb+8

    float acc[8][8];
#pragma unroll
    for (int i = 0; i < 8; i++)
#pragma unroll
        for (int j = 0; j < 8; j++) acc[i][j] = 0.f;

    const int nkt = K / BKK;
    float4 a0, a1, b0, b1;
    const float4 z4 = make_float4(0.f, 0.f, 0.f, 0.f);

#define FETCH(KT) {                                                                    \
    int k0 = (KT) * BKK;                                                               \
    a0 = (mb + ra      < M) ? *(const float4*)(A + (size_t)(mb + ra     ) * K + k0 + ca) : z4; \
    a1 = (mb + ra + 64 < M) ? *(const float4*)(A + (size_t)(mb + ra + 64) * K + k0 + ca) : z4; \
    b0 = *(const float4*)(W + (size_t)(k0 + rb    ) * N + nb + cb);                    \
    b1 = *(const float4*)(W + (size_t)(k0 + rb + 8) * N + nb + cb); }

#define STAGE(BUF) {                                                                   \
    As[BUF][ca + 0][ra] = a0.x; As[BUF][ca + 1][ra] = a0.y;                            \
    As[BUF][ca + 2][ra] = a0.z; As[BUF][ca + 3][ra] = a0.w;                            \
    As[BUF][ca + 0][ra + 64] = a1.x; As[BUF][ca + 1][ra + 64] = a1.y;                  \
    As[BUF][ca + 2][ra + 64] = a1.z; As[BUF][ca + 3][ra + 64] = a1.w;                  \
    *(float4*)&Bs[BUF][rb    ][cb] = b0;                                               \
    *(float4*)&Bs[BUF][rb + 8][cb] = b1; }

    FETCH(0); STAGE(0); __syncthreads();

    for (int kt = 0; kt < nkt; kt++) {
        int buf = kt & 1;
        if (kt + 1 < nkt) FETCH(kt + 1);
#pragma unroll
        for (int kk = 0; kk < BKK; kk++) {
            float ar[8], br[8];
            *(float4*)(ar)     = *(const float4*)&As[buf][kk][ty * 8];
            *(float4*)(ar + 4) = *(const float4*)&As[buf][kk][ty * 8 + 4];
            *(float4*)(br)     = *(const float4*)&Bs[buf][kk][tx * 8];
            *(float4*)(br + 4) = *(const float4*)&Bs[buf][kk][tx * 8 + 4];
#pragma unroll
            for (int i = 0; i < 8; i++)
#pragma unroll
                for (int j = 0; j < 8; j++) acc[i][j] += ar[i] * br[j];
        }
        if (kt + 1 < nkt) STAGE(buf ^ 1);
        __syncthreads();
    }
#undef FETCH
#undef STAGE

    float bsv[8];
#pragma unroll
    for (int j = 0; j < 8; j++) bsv[j] = bias[nb + tx * 8 + j];
#pragma unroll
    for (int i = 0; i < 8; i++) {
        int m = mb + ty * 8 + i;
        if (m >= M) continue;
        float vals[8];
#pragma unroll
        for (int j = 0; j < 8; j++) {
            float vv = acc[i][j] + bsv[j];
            if (ACT == 1) vv = 0.5f * vv * (1.f + erff(vv * 0.70710678118654752f));
            if (ACT == 2) vv = fmaxf(vv, 0.f);
            vals[j] = vv;
        }
        float* Cr = C + (size_t)m * N + nb + tx * 8;
        if (RES) {
            const float* Rr = Rp + (size_t)m * N + nb + tx * 8;
            float4 r0 = *(const float4*)Rr, r1 = *(const float4*)(Rr + 4);
            vals[0] += r0.x; vals[1] += r0.y; vals[2] += r0.z; vals[3] += r0.w;
            vals[4] += r1.x; vals[5] += r1.y; vals[6] += r1.z; vals[7] += r1.w;
        }
        *(float4*)Cr       = make_float4(vals[0], vals[1], vals[2], vals[3]);
        *(float4*)(Cr + 4) = make_float4(vals[4], vals[5], vals[6], vals[7]);
    }
}

// ---------------------------------------------------------------------------
// Flash-style causal attention, fp32. One CTA = (qblock of 64, head, batch),
// 64 threads (one query row each). Q row + O accum in registers; K/V/S in smem.
// Key blocks of 32 (warp0 loads K rows, warp1 loads V rows).
// ---------------------------------------------------------------------------
#define AKB 32

__global__ __launch_bounds__(64) void attn_kernel(
    const float* __restrict__ Q, const float* __restrict__ Km,
    const float* __restrict__ V, float* __restrict__ O)
{
    __shared__ float Ks[AKB][68];
    __shared__ float Vs[AKB][68];
    __shared__ float Ss[64][AKB + 1];

    const int t  = threadIdx.x;
    const int qb = blockIdx.x, h = blockIdx.y, b = blockIdx.z;
    const int qi = qb * 64 + t;
    const bool valid = (qi < S_);

    float qreg[DH_];
    if (valid) {
        const float4* qp = (const float4*)(Q + ((size_t)(b * S_ + qi)) * D_ + h * DH_);
#pragma unroll
        for (int i = 0; i < 16; i++) {
            float4 v4 = qp[i];
            qreg[4 * i + 0] = v4.x; qreg[4 * i + 1] = v4.y;
            qreg[4 * i + 2] = v4.z; qreg[4 * i + 3] = v4.w;
        }
    }
    float oacc[DH_];
#pragma unroll
    for (int d = 0; d < DH_; d++) oacc[d] = 0.f;
    float m = -1e30f, l = 0.f;

    const int nkb = 2 * qb + 2;   // key blocks covering [0, qb*64+64)
    for (int kb = 0; kb < nkb; kb++) {
        // cooperative load: warp0 -> K rows, warp1 -> V rows
        {
            int r = t & 31;
            int krow = kb * AKB + r;
            float* dst = (t < 32) ? &Ks[r][0] : &Vs[r][0];
            if (krow < S_) {
                const float4* src = (const float4*)(((t < 32) ? Km : V)
                                    + ((size_t)(b * S_ + krow)) * D_ + h * DH_);
                float4* d4 = (float4*)dst;
#pragma unroll
                for (int i = 0; i < 16; i++) d4[i] = src[i];
            } else {
                float4* d4 = (float4*)dst;
#pragma unroll
                for (int i = 0; i < 16; i++) d4[i] = make_float4(0.f, 0.f, 0.f, 0.f);
            }
        }
        __syncthreads();

        float bm = -1e30f;
#pragma unroll 4
        for (int j = 0; j < AKB; j++) {
            float sc = -1e30f;
            int kidx = kb * AKB + j;
            if (valid && kidx <= qi) {
                float a = 0.f;
                const float4* kp = (const float4*)&Ks[j][0];
#pragma unroll
                for (int i = 0; i < 16; i++) {
                    float4 kv = kp[i];
                    a += qreg[4 * i + 0] * kv.x + qreg[4 * i + 1] * kv.y
                       + qreg[4 * i + 2] * kv.z + qreg[4 * i + 3] * kv.w;
                }
                sc = a * 0.125f;   // 1/sqrt(64)
            }
            Ss[t][j] = sc;
            bm = fmaxf(bm, sc);
        }
        if (valid) {
            float newm = fmaxf(m, bm);
            float fac = __expf(m - newm);
            m = newm;
            l *= fac;
#pragma unroll
            for (int d = 0; d < DH_; d++) oacc[d] *= fac;
            for (int j = 0; j < AKB; j++) {
                float p = __expf(Ss[t][j] - m);
                l += p;
                const float4* vp = (const float4*)&Vs[j][0];
#pragma unroll
                for (int i = 0; i < 16; i++) {
                    float4 vv = vp[i];
                    oacc[4 * i + 0] += p * vv.x; oacc[4 * i + 1] += p * vv.y;
                    oacc[4 * i + 2] += p * vv.z; oacc[4 * i + 3] += p * vv.w;
                }
            }
        }
        __syncthreads();
    }

    if (valid) {
        float inv = 1.f / l;
        float4* op = (float4*)(O + ((size_t)(b * S_ + qi)) * D_ + h * DH_);
#pragma unroll
        for (int i = 0; i < 16; i++)
            op[i] = make_float4(oacc[4 * i + 0] * inv, oacc[4 * i + 1] * inv,
                                oacc[4 * i + 2] * inv, oacc[4 * i + 3] * inv);
    }
}

// ---------------------------------------------------------------------------
// Gather head rows
// ---------------------------------------------------------------------------
__global__ __launch_bounds__(256) void gather_obs_kernel(
    const float* __restrict__ Xf, float* __restrict__ Xo)
{
    int i = blockIdx.x;               // 0 .. B*960-1
    int b = i / NOBS_;
    int r = i - b * NOBS_;
    int blk = r >> 4, rr = r & 15;
    int s = blk * TPB_ + (rr < 15 ? rr : 16);
    int t = threadIdx.x;
    ((float4*)(Xo + (size_t)i * D_))[t] =
        ((const float4*)(Xf + ((size_t)(b * S_ + s)) * D_))[t];
}

__global__ __launch_bounds__(256) void gather_act_kernel(
    const float* __restrict__ Xf, float* __restrict__ Xe)
{
    int i = blockIdx.x;               // 0 .. B*60-1
    int b = i / NACT_;
    int j = i - b * NACT_;
    int s = j * TPB_ + (TPB_ - 1);
    int t = threadIdx.x;
    ((float4*)(Xe + (size_t)i * D_))[t] =
        ((const float4*)(Xf + ((size_t)(b * S_ + s)) * D_))[t];
}

// ---------------------------------------------------------------------------
// Tiny ends head: out[row, 0:2] = t2[row,:] @ he2 + be2  (K=1024, N=2)
// ---------------------------------------------------------------------------
__global__ __launch_bounds__(256) void ends_kernel(
    const float* __restrict__ T2, const float* __restrict__ he2,
    const float* __restrict__ be2, float* __restrict__ out)
{
    int row = blockIdx.x;
    int t = threadIdx.x;
    float a0 = 0.f, a1 = 0.f;
    for (int k = t; k < D_; k += 256) {
        float x = T2[(size_t)row * D_ + k];
        a0 += x * he2[2 * k + 0];
        a1 += x * he2[2 * k + 1];
    }
    __shared__ float r0[256], r1[256];
    r0[t] = a0; r1[t] = a1;
    __syncthreads();
    for (int st = 128; st > 0; st >>= 1) {
        if (t < st) { r0[t] += r0[t + st]; r1[t] += r1[t + st]; }
        __syncthreads();
    }
    if (t == 0) {
        out[(size_t)row * 2 + 0] = r0[0] + be2[0];
        out[(size_t)row * 2 + 1] = r1[0] + be2[1];
    }
}

// ---------------------------------------------------------------------------
// Host launcher
// ---------------------------------------------------------------------------
static void run_gemm(int act, bool res,
                     const float* A, const float* W, const float* bias,
                     const float* R, float* C, int M, int N, int K)
{
    dim3 g(N / BN, (M + BM - 1) / BM), blk(256);
    if (res)            sgemm_kernel<0, true ><<<g, blk>>>(A, W, bias, R,       C, M, N, K);
    else if (act == 0)  sgemm_kernel<0, false><<<g, blk>>>(A, W, bias, nullptr, C, M, N, K);
    else if (act == 1)  sgemm_kernel<1, false><<<g, blk>>>(A, W, bias, nullptr, C, M, N, K);
    else                sgemm_kernel<2, false><<<g, blk>>>(A, W, bias, nullptr, C, M, N, K);
}

extern "C" void kernel_launch(void* const* d_in, const int* in_sizes, int n_in,
                              void* d_out, int out_size)
{
    (void)in_sizes; (void)n_in; (void)out_size;
    const int*   tokens  = (const int*)  d_in[0];
    const float* pos_emb = (const float*)d_in[1];
    const float* emb_obs = (const float*)d_in[2];
    const float* emb_act = (const float*)d_in[3];
    const float* ln1_g   = (const float*)d_in[4];
    const float* ln1_b   = (const float*)d_in[5];
    const float* wq      = (const float*)d_in[6];
    const float* bq      = (const float*)d_in[7];
    const float* wk      = (const float*)d_in[8];
    const float* bk      = (const float*)d_in[9];
    const float* wv      = (const float*)d_in[10];
    const float* bv      = (const float*)d_in[11];
    const float* wo      = (const float*)d_in[12];
    const float* bo      = (const float*)d_in[13];
    const float* ln2_g   = (const float*)d_in[14];
    const float* ln2_b   = (const float*)d_in[15];
    const float* w1      = (const float*)d_in[16];
    const float* b1      = (const float*)d_in[17];
    const float* w2      = (const float*)d_in[18];
    const float* b2      = (const float*)d_in[19];
    const float* lnf_g   = (const float*)d_in[20];
    const float* lnf_b   = (const float*)d_in[21];
    const float* ho1     = (const float*)d_in[22];
    const float* bo1     = (const float*)d_in[23];
    const float* ho2     = (const float*)d_in[24];
    const float* bo2     = (const float*)d_in[25];
    const float* he1     = (const float*)d_in[26];
    const float* be1     = (const float*)d_in[27];
    const float* he2     = (const float*)d_in[28];
    const float* be2     = (const float*)d_in[29];
    float* out = (float*)d_out;

    float *x, *h, *q, *k, *v, *o, *mlp, *xo, *t1, *xe, *t2;
    cudaGetSymbolAddress((void**)&x,   g_x);
    cudaGetSymbolAddress((void**)&h,   g_h);
    cudaGetSymbolAddress((void**)&q,   g_q);
    cudaGetSymbolAddress((void**)&k,   g_k);
    cudaGetSymbolAddress((void**)&v,   g_v);
    cudaGetSymbolAddress((void**)&o,   g_o);
    cudaGetSymbolAddress((void**)&mlp, g_mlp);
    cudaGetSymbolAddress((void**)&xo,  g_xo);
    cudaGetSymbolAddress((void**)&t1,  g_t1);
    cudaGetSymbolAddress((void**)&xe,  g_xe);
    cudaGetSymbolAddress((void**)&t2,  g_t2);

    // Embedding
    embed_kernel<<<BS_, 256>>>(tokens, pos_emb, emb_obs, emb_act, x);

    // Transformer layers
    for (int i = 0; i < L_; i++) {
        const size_t dd = (size_t)D_ * D_;
        ln_kernel<<<BS_, 256>>>(x, ln1_g + i * D_, ln1_b + i * D_, h);
        run_gemm(0, false, h, wq + i * dd, bq + i * D_, nullptr, q, BS_, D_, D_);
        run_gemm(0, false, h, wk + i * dd, bk + i * D_, nullptr, k, BS_, D_, D_);
        run_gemm(0, false, h, wv + i * dd, bv + i * D_, nullptr, v, BS_, D_, D_);
        attn_kernel<<<dim3(16, H_, B_), 64>>>(q, k, v, o);
        run_gemm(0, true,  o, wo + i * dd, bo + i * D_, x, x, BS_, D_, D_);
        ln_kernel<<<BS_, 256>>>(x, ln2_g + i * D_, ln2_b + i * D_, h);
        run_gemm(1, false, h,   w1 + i * (size_t)D_ * D4_, b1 + i * D4_, nullptr, mlp, BS_, D4_, D_);
        run_gemm(0, true,  mlp, w2 + i * (size_t)D4_ * D_, b2 + i * D_,  x,       x,   BS_, D_, D4_);
    }

    // Final LN + heads
    ln_kernel<<<BS_, 256>>>(x, lnf_g, lnf_b, h);
    gather_obs_kernel<<<B_ * NOBS_, 256>>>(h, xo);
    gather_act_kernel<<<B_ * NACT_, 256>>>(h, xe);

    // obs head: relu(xo@ho1+bo1) @ ho2 + bo2 -> d_out[0 : B*960*4096]
    run_gemm(2, false, xo, ho1, bo1, nullptr, t1, B_ * NOBS_, D_, D_);
    run_gemm(0, false, t1, ho2, bo2, nullptr, out, B_ * NOBS_, VOBS_, D_);

    // ends head: relu(xe@he1+be1) @ he2 + be2 -> d_out[B*960*4096 : +B*60*2]
    run_gemm(2, false, xe, he1, be1, nullptr, t2, B_ * NACT_, D_, D_);
    ends_kernel<<<B_ * NACT_, 256>>>(t2, he2, be2, out + (size_t)B_ * NOBS_ * VOBS_);
}

// round 2
// speedup vs baseline: 1.9886x; 1.9886x over previous
#include <cuda_runtime.h>
#include <cuda_bf16.h>
#include <math.h>
#include <stdint.h>

// ---------------------------------------------------------------------------
// Problem constants
// ---------------------------------------------------------------------------
#define B_    4
#define S_    1020
#define D_    1024
#define H_    16
#define L_    4
#define DH_   64
#define TPB_  17
#define BS_   (B_ * S_)        // 4080 rows
#define VOBS_ 4096
#define VACT_ 16
#define D4_   4096
#define NOBS_ 960
#define NACT_ 60
#define EPS_  1e-3f

typedef __nv_bfloat16 bf16;

// ---------------------------------------------------------------------------
// Scratch (static __device__ arrays -- no runtime allocation allowed)
// ---------------------------------------------------------------------------
__device__ float g_x [BS_ * D_];        // residual stream (fp32)
__device__ float g_hf[BS_ * D_];        // final-LN output (fp32)
__device__ float g_q [BS_ * D_];
__device__ float g_k [BS_ * D_];
__device__ float g_v [BS_ * D_];

// split activations
__device__ bf16 g_hh[BS_ * D_],  g_hl[BS_ * D_];    // LN output
__device__ bf16 g_oh[BS_ * D_],  g_ol[BS_ * D_];    // attention output
__device__ bf16 g_mh[BS_ * D4_], g_ml[BS_ * D4_];   // MLP hidden
__device__ bf16 g_xoh[B_ * NOBS_ * D_], g_xol[B_ * NOBS_ * D_];
__device__ bf16 g_t1h[B_ * NOBS_ * D_], g_t1l[B_ * NOBS_ * D_];
__device__ bf16 g_xeh[B_ * NACT_ * D_], g_xel[B_ * NACT_ * D_];
__device__ bf16 g_t2h[B_ * NACT_ * D_], g_t2l[B_ * NACT_ * D_];

// split weights
__device__ bf16 g_wqh[L_ * D_ * D_],  g_wql[L_ * D_ * D_];
__device__ bf16 g_wkh[L_ * D_ * D_],  g_wkl[L_ * D_ * D_];
__device__ bf16 g_wvh[L_ * D_ * D_],  g_wvl[L_ * D_ * D_];
__device__ bf16 g_woh[L_ * D_ * D_],  g_wol[L_ * D_ * D_];
__device__ bf16 g_w1h[L_ * D_ * D4_], g_w1l[L_ * D_ * D4_];
__device__ bf16 g_w2h[L_ * D4_ * D_], g_w2l[L_ * D4_ * D_];
__device__ bf16 g_ho1h[D_ * D_],    g_ho1l[D_ * D_];
__device__ bf16 g_ho2h[D_ * VOBS_], g_ho2l[D_ * VOBS_];
__device__ bf16 g_he1h[D_ * D_],    g_he1l[D_ * D_];

// ---------------------------------------------------------------------------
// Helpers
// ---------------------------------------------------------------------------
__device__ __forceinline__ void split2(float x, bf16& h, bf16& l) {
    h = __float2bfloat16_rn(x);
    l = __float2bfloat16_rn(x - __bfloat162float(h));
}

__device__ __forceinline__ void ldsm4(uint32_t* r, uint32_t a) {
    asm volatile("ldmatrix.sync.aligned.m8n8.x4.shared.b16 {%0,%1,%2,%3},[%4];\n"
        : "=r"(r[0]), "=r"(r[1]), "=r"(r[2]), "=r"(r[3]) : "r"(a));
}
__device__ __forceinline__ void ldsm4t(uint32_t* r, uint32_t a) {
    asm volatile("ldmatrix.sync.aligned.m8n8.x4.trans.shared.b16 {%0,%1,%2,%3},[%4];\n"
        : "=r"(r[0]), "=r"(r[1]), "=r"(r[2]), "=r"(r[3]) : "r"(a));
}
__device__ __forceinline__ void mma_bf16(float* c, const uint32_t* a, const uint32_t* b) {
    asm volatile("mma.sync.aligned.m16n8k16.row.col.f32.bf16.bf16.f32 "
        "{%0,%1,%2,%3},{%4,%5,%6,%7},{%8,%9},{%0,%1,%2,%3};\n"
        : "+f"(c[0]), "+f"(c[1]), "+f"(c[2]), "+f"(c[3])
        : "r"(a[0]), "r"(a[1]), "r"(a[2]), "r"(a[3]), "r"(b[0]), "r"(b[1]));
}
__device__ __forceinline__ void cpasync16(uint32_t dst, const void* src) {
    asm volatile("cp.async.ca.shared.global [%0],[%1],16;\n" :: "r"(dst), "l"(src));
}

// ---------------------------------------------------------------------------
// f32 -> (hi, lo) bf16 split (n divisible by 1024)
// ---------------------------------------------------------------------------
__global__ __launch_bounds__(256) void split_kernel(
    const float* __restrict__ X, bf16* __restrict__ Xh, bf16* __restrict__ Xl)
{
    int i = blockIdx.x * 256 + threadIdx.x;        // float4 index
    float4 v = ((const float4*)X)[i];
    bf16 h0, l0, h1, l1, h2, l2, h3, l3;
    split2(v.x, h0, l0); split2(v.y, h1, l1);
    split2(v.z, h2, l2); split2(v.w, h3, l3);
    __nv_bfloat162 a, b;
    a.x = h0; a.y = h1; b.x = h2; b.y = h3;
    ((__nv_bfloat162*)Xh)[2 * i] = a; ((__nv_bfloat162*)Xh)[2 * i + 1] = b;
    a.x = l0; a.y = l1; b.x = l2; b.y = l3;
    ((__nv_bfloat162*)Xl)[2 * i] = a; ((__nv_bfloat162*)Xl)[2 * i + 1] = b;
}

// ---------------------------------------------------------------------------
// Embedding
// ---------------------------------------------------------------------------
__global__ __launch_bounds__(256) void embed_kernel(
    const int* __restrict__ tok, const float* __restrict__ pos_emb,
    const float* __restrict__ eobs, const float* __restrict__ eact,
    float* __restrict__ X)
{
    int row = blockIdx.x;
    int b = row / S_;
    int s = row - b * S_;
    int t = threadIdx.x;
    int tk = tok[row];
    bool obs = (s % TPB_) < (TPB_ - 1);
    const float4* e = (const float4*)(obs ? (eobs + (size_t)min(tk, VOBS_ - 1) * D_)
                                          : (eact + (size_t)min(tk, VACT_ - 1) * D_));
    const float4* p = (const float4*)(pos_emb + (size_t)s * D_);
    float4 a = e[t], c = p[t];
    ((float4*)(X + (size_t)row * D_))[t] =
        make_float4(a.x + c.x, a.y + c.y, a.z + c.z, a.w + c.w);
}

// ---------------------------------------------------------------------------
// LayerNorm. SPLIT: write (hi,lo) bf16; else write f32.
// ---------------------------------------------------------------------------
template <bool SPLIT>
__global__ __launch_bounds__(256) void ln_kernel(
    const float* __restrict__ X, const float* __restrict__ g,
    const float* __restrict__ bb, float* __restrict__ Y,
    bf16* __restrict__ Yh, bf16* __restrict__ Yl)
{
    int row = blockIdx.x;
    int t = threadIdx.x;
    const float4* xp = (const float4*)(X + (size_t)row * D_);
    float4 v = xp[t];
    float s  = v.x + v.y + v.z + v.w;
    float ss = v.x * v.x + v.y * v.y + v.z * v.z + v.w * v.w;
#pragma unroll
    for (int off = 16; off > 0; off >>= 1) {
        s  += __shfl_xor_sync(0xffffffffu, s,  off);
        ss += __shfl_xor_sync(0xffffffffu, ss, off);
    }
    __shared__ float smA[8], smB[8];
    int lane = t & 31, wid = t >> 5;
    if (lane == 0) { smA[wid] = s; smB[wid] = ss; }
    __syncthreads();
    float tot = 0.f, tot2 = 0.f;
#pragma unroll
    for (int i = 0; i < 8; i++) { tot += smA[i]; tot2 += smB[i]; }
    float mean = tot * (1.f / D_);
    float var  = tot2 * (1.f / D_) - mean * mean;
    float rstd = rsqrtf(var + EPS_);
    float4 gv = ((const float4*)g)[t], bv = ((const float4*)bb)[t];
    float4 o;
    o.x = (v.x - mean) * rstd * gv.x + bv.x;
    o.y = (v.y - mean) * rstd * gv.y + bv.y;
    o.z = (v.z - mean) * rstd * gv.z + bv.z;
    o.w = (v.w - mean) * rstd * gv.w + bv.w;
    if (SPLIT) {
        size_t base = (size_t)row * D_ / 2 + 2 * t;   // bfloat162 index
        bf16 h0, l0, h1, l1, h2, l2, h3, l3;
        split2(o.x, h0, l0); split2(o.y, h1, l1);
        split2(o.z, h2, l2); split2(o.w, h3, l3);
        __nv_bfloat162 p0, p1;
        p0.x = h0; p0.y = h1; p1.x = h2; p1.y = h3;
        ((__nv_bfloat162*)Yh)[base] = p0; ((__nv_bfloat162*)Yh)[base + 1] = p1;
        p0.x = l0; p0.y = l1; p1.x = l2; p1.y = l3;
        ((__nv_bfloat162*)Yl)[base] = p0; ((__nv_bfloat162*)Yl)[base + 1] = p1;
    } else {
        ((float4*)(Y + (size_t)row * D_))[t] = o;
    }
}

// ---------------------------------------------------------------------------
// Split-bf16 3-term tensor-core GEMM.
// C[M,N] = act(sum_k (Ah+Al)[m,k] * (Bh+Bl)[k,n] + bias[n]) (+R)
// block 128x128, BK=32, 256 thr, warp tile 64x32, 3-stage cp.async.
// ---------------------------------------------------------------------------
#define STAGES     3
#define AH_STR     40                         // bf16 elems per A smem row
#define B_STR      136                        // bf16 elems per B smem row
#define A_BYTES    (128 * AH_STR * 2)         // 10240
#define Bt_BYTES   (32 * B_STR * 2)           // 8704
#define STAGE_BYTES (2 * A_BYTES + 2 * Bt_BYTES)   // 37888
#define GEMM_SMEM  (STAGES * STAGE_BYTES)          // 113664

template <int ACT, bool RES, bool OUTF32, bool OUTSPLIT>
__global__ __launch_bounds__(256, 1) void gemm3_kernel(
    const bf16* __restrict__ Ah, const bf16* __restrict__ Al,
    const bf16* __restrict__ Bh, const bf16* __restrict__ Bl,
    const float* __restrict__ bias, const float* __restrict__ Rp,
    float* __restrict__ C, bf16* __restrict__ Ch, bf16* __restrict__ Cl,
    int M, int N, int K)
{
    extern __shared__ char smem[];
    const uint32_t smem_u = (uint32_t)__cvta_generic_to_shared(smem);
    const int t = threadIdx.x;
    const int mb = blockIdx.y * 128, nb = blockIdx.x * 128;
    const int wid = t >> 5, lane = t & 31;
    const int wm = (wid >> 2) * 64, wn = (wid & 3) * 32;

    float acc[4][4][4];
#pragma unroll
    for (int i = 0; i < 4; i++)
#pragma unroll
        for (int j = 0; j < 4; j++)
#pragma unroll
            for (int kq = 0; kq < 4; kq++) acc[i][j][kq] = 0.f;

    const int nkt = K / 32;

#define LOAD_STAGE(KT, SS) {                                                     \
    uint32_t sb_ = smem_u + (SS) * STAGE_BYTES;                                  \
    int k0_ = (KT) * 32;                                                         \
    _Pragma("unroll")                                                            \
    for (int j_ = 0; j_ < 2; j_++) {                                             \
        int c_ = t + j_ * 256;                                                   \
        int row_ = c_ >> 2, kc_ = c_ & 3;                                        \
        int rg_ = mb + row_; if (rg_ > M - 1) rg_ = M - 1;                       \
        uint32_t dst_ = sb_ + row_ * (AH_STR * 2) + kc_ * 16;                    \
        cpasync16(dst_,           Ah + (size_t)rg_ * K + k0_ + kc_ * 8);         \
        cpasync16(dst_ + A_BYTES, Al + (size_t)rg_ * K + k0_ + kc_ * 8);         \
    }                                                                            \
    _Pragma("unroll")                                                            \
    for (int j_ = 0; j_ < 2; j_++) {                                             \
        int c_ = t + j_ * 256;                                                   \
        int row_ = c_ >> 4, nc_ = c_ & 15;                                       \
        uint32_t dst_ = sb_ + 2 * A_BYTES + row_ * (B_STR * 2) + nc_ * 16;       \
        cpasync16(dst_,            Bh + (size_t)(k0_ + row_) * N + nb + nc_ * 8);\
        cpasync16(dst_ + Bt_BYTES, Bl + (size_t)(k0_ + row_) * N + nb + nc_ * 8);\
    }                                                                            \
    asm volatile("cp.async.commit_group;\n"); }

    LOAD_STAGE(0, 0);
    LOAD_STAGE(1, 1);

    for (int kt = 0; kt < nkt; kt++) {
        int s = kt % STAGES;
        asm volatile("cp.async.wait_group %0;\n" :: "n"(STAGES - 2));
        __syncthreads();
        if (kt + 2 < nkt) { LOAD_STAGE(kt + 2, (kt + 2) % STAGES); }
        uint32_t sb = smem_u + s * STAGE_BYTES;
#pragma unroll
        for (int ks = 0; ks < 2; ks++) {
            uint32_t ah[4][4], al[4][4], bh[2][4], bl[2][4];
#pragma unroll
            for (int i = 0; i < 4; i++) {
                uint32_t addr = sb + ((wm + i * 16 + (lane & 15)) * AH_STR
                                      + ks * 16 + (lane >> 4) * 8) * 2;
                ldsm4(ah[i], addr);
                ldsm4(al[i], addr + A_BYTES);
            }
#pragma unroll
            for (int p = 0; p < 2; p++) {
                uint32_t addr = sb + 2 * A_BYTES
                              + ((ks * 16 + (lane & 15)) * B_STR
                                 + wn + p * 16 + (lane >> 4) * 8) * 2;
                ldsm4t(bh[p], addr);
                ldsm4t(bl[p], addr + Bt_BYTES);
            }
#pragma unroll
            for (int i = 0; i < 4; i++)
#pragma unroll
                for (int nt = 0; nt < 4; nt++) {
                    const uint32_t* bhp = &bh[nt >> 1][(nt & 1) * 2];
                    const uint32_t* blp = &bl[nt >> 1][(nt & 1) * 2];
                    mma_bf16(acc[i][nt], ah[i], bhp);
                    mma_bf16(acc[i][nt], ah[i], blp);
                    mma_bf16(acc[i][nt], al[i], bhp);
                }
        }
    }
#undef LOAD_STAGE

    // Epilogue
    const int r0 = lane >> 2;
    const int cc = (lane & 3) * 2;
#pragma unroll
    for (int i = 0; i < 4; i++) {
#pragma unroll
        for (int half = 0; half < 2; half++) {
            int m = mb + wm + i * 16 + r0 + half * 8;
            if (m >= M) continue;
#pragma unroll
            for (int nt = 0; nt < 4; nt++) {
                int n = nb + wn + nt * 8 + cc;
                float v0 = acc[i][nt][half * 2 + 0] + bias[n];
                float v1 = acc[i][nt][half * 2 + 1] + bias[n + 1];
                if (ACT == 1) {
                    v0 = 0.5f * v0 * (1.f + erff(v0 * 0.70710678118654752f));
                    v1 = 0.5f * v1 * (1.f + erff(v1 * 0.70710678118654752f));
                }
                if (ACT == 2) { v0 = fmaxf(v0, 0.f); v1 = fmaxf(v1, 0.f); }
                if (RES) {
                    float2 rr = *(const float2*)(Rp + (size_t)m * N + n);
                    v0 += rr.x; v1 += rr.y;
                }
                if (OUTF32) {
                    *(float2*)(C + (size_t)m * N + n) = make_float2(v0, v1);
                }
                if (OUTSPLIT) {
                    bf16 h0, l0, h1, l1;
                    split2(v0, h0, l0); split2(v1, h1, l1);
                    __nv_bfloat162 hp, lp;
                    hp.x = h0; hp.y = h1; lp.x = l0; lp.y = l1;
                    *(__nv_bfloat162*)(Ch + (size_t)m * N + n) = hp;
                    *(__nv_bfloat162*)(Cl + (size_t)m * N + n) = lp;
                }
            }
        }
    }
}

// ---------------------------------------------------------------------------
// Flash-style causal attention, fp32 math, split-bf16 output.
// ---------------------------------------------------------------------------
#define AKB 32

__global__ __launch_bounds__(64) void attn_kernel(
    const float* __restrict__ Q, const float* __restrict__ Km,
    const float* __restrict__ V, bf16* __restrict__ Oh, bf16* __restrict__ Ol)
{
    __shared__ float Ks[AKB][68];
    __shared__ float Vs[AKB][68];
    __shared__ float Ss[64][AKB + 1];

    const int t  = threadIdx.x;
    const int qb = blockIdx.x, h = blockIdx.y, b = blockIdx.z;
    const int qi = qb * 64 + t;
    const bool valid = (qi < S_);

    float qreg[DH_];
    if (valid) {
        const float4* qp = (const float4*)(Q + ((size_t)(b * S_ + qi)) * D_ + h * DH_);
#pragma unroll
        for (int i = 0; i < 16; i++) {
            float4 v4 = qp[i];
            qreg[4 * i + 0] = v4.x; qreg[4 * i + 1] = v4.y;
            qreg[4 * i + 2] = v4.z; qreg[4 * i + 3] = v4.w;
        }
    }
    float oacc[DH_];
#pragma unroll
    for (int d = 0; d < DH_; d++) oacc[d] = 0.f;
    float m = -1e30f, l = 0.f;

    const int nkb = 2 * qb + 2;
    for (int kb = 0; kb < nkb; kb++) {
        {
            int r = t & 31;
            int krow = kb * AKB + r;
            float* dst = (t < 32) ? &Ks[r][0] : &Vs[r][0];
            float4* d4 = (float4*)dst;
            if (krow < S_) {
                const float4* src = (const float4*)(((t < 32) ? Km : V)
                                    + ((size_t)(b * S_ + krow)) * D_ + h * DH_);
#pragma unroll
                for (int i = 0; i < 16; i++) d4[i] = src[i];
            } else {
#pragma unroll
                for (int i = 0; i < 16; i++) d4[i] = make_float4(0.f, 0.f, 0.f, 0.f);
            }
        }
        __syncthreads();

        float bm = -1e30f;
#pragma unroll 4
        for (int j = 0; j < AKB; j++) {
            float sc = -1e30f;
            int kidx = kb * AKB + j;
            if (valid && kidx <= qi) {
                float a = 0.f;
                const float4* kp = (const float4*)&Ks[j][0];
#pragma unroll
                for (int i = 0; i < 16; i++) {
                    float4 kv = kp[i];
                    a += qreg[4 * i + 0] * kv.x + qreg[4 * i + 1] * kv.y
                       + qreg[4 * i + 2] * kv.z + qreg[4 * i + 3] * kv.w;
                }
                sc = a * 0.125f;
            }
            Ss[t][j] = sc;
            bm = fmaxf(bm, sc);
        }
        if (valid) {
            float newm = fmaxf(m, bm);
            float fac = __expf(m - newm);
            m = newm;
            l *= fac;
#pragma unroll
            for (int d = 0; d < DH_; d++) oacc[d] *= fac;
            for (int j = 0; j < AKB; j++) {
                float p = __expf(Ss[t][j] - m);
                l += p;
                const float4* vp = (const float4*)&Vs[j][0];
#pragma unroll
                for (int i = 0; i < 16; i++) {
                    float4 vv = vp[i];
                    oacc[4 * i + 0] += p * vv.x; oacc[4 * i + 1] += p * vv.y;
                    oacc[4 * i + 2] += p * vv.z; oacc[4 * i + 3] += p * vv.w;
                }
            }
        }
        __syncthreads();
    }

    if (valid) {
        float inv = 1.f / l;
        size_t base = ((size_t)(b * S_ + qi)) * D_ + h * DH_;
#pragma unroll
        for (int i = 0; i < 32; i++) {
            float v0 = oacc[2 * i] * inv, v1 = oacc[2 * i + 1] * inv;
            bf16 h0, l0, h1, l1;
            split2(v0, h0, l0); split2(v1, h1, l1);
            __nv_bfloat162 hp, lp;
            hp.x = h0; hp.y = h1; lp.x = l0; lp.y = l1;
            *(__nv_bfloat162*)(Oh + base + 2 * i) = hp;
            *(__nv_bfloat162*)(Ol + base + 2 * i) = lp;
        }
    }
}

// ---------------------------------------------------------------------------
// Gather head rows (f32 -> split bf16)
// ---------------------------------------------------------------------------
__global__ __launch_bounds__(256) void gather_obs_kernel(
    const float* __restrict__ Xf, bf16* __restrict__ Xh, bf16* __restrict__ Xl)
{
    int i = blockIdx.x;
    int b = i / NOBS_;
    int r = i - b * NOBS_;
    int blk = r >> 4, rr = r & 15;
    int s = blk * TPB_ + (rr < 15 ? rr : 16);
    int t = threadIdx.x;
    float4 v = ((const float4*)(Xf + ((size_t)(b * S_ + s)) * D_))[t];
    bf16 h0, l0, h1, l1, h2, l2, h3, l3;
    split2(v.x, h0, l0); split2(v.y, h1, l1);
    split2(v.z, h2, l2); split2(v.w, h3, l3);
    size_t base = (size_t)i * D_ / 2 + 2 * t;
    __nv_bfloat162 p0, p1;
    p0.x = h0; p0.y = h1; p1.x = h2; p1.y = h3;
    ((__nv_bfloat162*)Xh)[base] = p0; ((__nv_bfloat162*)Xh)[base + 1] = p1;
    p0.x = l0; p0.y = l1; p1.x = l2; p1.y = l3;
    ((__nv_bfloat162*)Xl)[base] = p0; ((__nv_bfloat162*)Xl)[base + 1] = p1;
}

__global__ __launch_bounds__(256) void gather_act_kernel(
    const float* __restrict__ Xf, bf16* __restrict__ Xh, bf16* __restrict__ Xl)
{
    int i = blockIdx.x;
    int b = i / NACT_;
    int j = i - b * NACT_;
    int s = j * TPB_ + (TPB_ - 1);
    int t = threadIdx.x;
    float4 v = ((const float4*)(Xf + ((size_t)(b * S_ + s)) * D_))[t];
    bf16 h0, l0, h1, l1, h2, l2, h3, l3;
    split2(v.x, h0, l0); split2(v.y, h1, l1);
    split2(v.z, h2, l2); split2(v.w, h3, l3);
    size_t base = (size_t)i * D_ / 2 + 2 * t;
    __nv_bfloat162 p0, p1;
    p0.x = h0; p0.y = h1; p1.x = h2; p1.y = h3;
    ((__nv_bfloat162*)Xh)[base] = p0; ((__nv_bfloat162*)Xh)[base + 1] = p1;
    p0.x = l0; p0.y = l1; p1.x = l2; p1.y = l3;
    ((__nv_bfloat162*)Xl)[base] = p0; ((__nv_bfloat162*)Xl)[base + 1] = p1;
}

// ---------------------------------------------------------------------------
// Ends head (K=1024, N=2) from split-bf16 input
// ---------------------------------------------------------------------------
__global__ __launch_bounds__(256) void ends_kernel(
    const bf16* __restrict__ T2h, const bf16* __restrict__ T2l,
    const float* __restrict__ he2, const float* __restrict__ be2,
    float* __restrict__ out)
{
    int row = blockIdx.x;
    int t = threadIdx.x;
    float a0 = 0.f, a1 = 0.f;
    for (int k = t; k < D_; k += 256) {
        float x = __bfloat162float(T2h[(size_t)row * D_ + k])
                + __bfloat162float(T2l[(size_t)row * D_ + k]);
        a0 += x * he2[2 * k + 0];
        a1 += x * he2[2 * k + 1];
    }
    __shared__ float r0[256], r1[256];
    r0[t] = a0; r1[t] = a1;
    __syncthreads();
    for (int st = 128; st > 0; st >>= 1) {
        if (t < st) { r0[t] += r0[t + st]; r1[t] += r1[t + st]; }
        __syncthreads();
    }
    if (t == 0) {
        out[(size_t)row * 2 + 0] = r0[0] + be2[0];
        out[(size_t)row * 2 + 1] = r1[0] + be2[1];
    }
}

// ---------------------------------------------------------------------------
// Host launcher
// ---------------------------------------------------------------------------
template <int ACT, bool RES, bool OUTF32, bool OUTSPLIT>
static void launch_gemm3(const bf16* Ah, const bf16* Al,
                         const bf16* Bh, const bf16* Bl,
                         const float* bias, const float* R,
                         float* C, bf16* Ch, bf16* Cl,
                         int M, int N, int K)
{
    static bool attr_done = false;
    (void)attr_done;
    cudaFuncSetAttribute(gemm3_kernel<ACT, RES, OUTF32, OUTSPLIT>,
                         cudaFuncAttributeMaxDynamicSharedMemorySize, GEMM_SMEM);
    dim3 g(N / 128, (M + 127) / 128), blk(256);
    gemm3_kernel<ACT, RES, OUTF32, OUTSPLIT><<<g, blk, GEMM_SMEM>>>(
        Ah, Al, Bh, Bl, bias, R, C, Ch, Cl, M, N, K);
}

static void run_split(const float* X, bf16* Xh, bf16* Xl, size_t n)
{
    split_kernel<<<(unsigned)(n / 1024), 256>>>(X, Xh, Xl);
}

extern "C" void kernel_launch(void* const* d_in, const int* in_sizes, int n_in,
                              void* d_out, int out_size)
{
    (void)in_sizes; (void)n_in; (void)out_size;
    const int*   tokens  = (const int*)  d_in[0];
    const float* pos_emb = (const float*)d_in[1];
    const float* emb_obs = (const float*)d_in[2];
    const float* emb_act = (const float*)d_in[3];
    const float* ln1_g   = (const float*)d_in[4];
    const float* ln1_b   = (const float*)d_in[5];
    const float* wq      = (const float*)d_in[6];
    const float* bq      = (const float*)d_in[7];
    const float* wk      = (const float*)d_in[8];
    const float* bk      = (const float*)d_in[9];
    const float* wv      = (const float*)d_in[10];
    const float* bv      = (const float*)d_in[11];
    const float* wo      = (const float*)d_in[12];
    const float* bo      = (const float*)d_in[13];
    const float* ln2_g   = (const float*)d_in[14];
    const float* ln2_b   = (const float*)d_in[15];
    const float* w1      = (const float*)d_in[16];
    const float* b1      = (const float*)d_in[17];
    const float* w2      = (const float*)d_in[18];
    const float* b2      = (const float*)d_in[19];
    const float* lnf_g   = (const float*)d_in[20];
    const float* lnf_b   = (const float*)d_in[21];
    const float* ho1     = (const float*)d_in[22];
    const float* bo1     = (const float*)d_in[23];
    const float* ho2     = (const float*)d_in[24];
    const float* bo2     = (const float*)d_in[25];
    const float* he1     = (const float*)d_in[26];
    const float* be1     = (const float*)d_in[27];
    const float* he2     = (const float*)d_in[28];
    const float* be2     = (const float*)d_in[29];
    float* out = (float*)d_out;

    float *x, *hf, *q, *k, *v;
    bf16 *hh, *hl, *oh, *ol, *mh, *ml, *xoh, *xol, *t1h, *t1l, *xeh, *xel, *t2h, *t2l;
    bf16 *wqh, *wql, *wkh, *wkl, *wvh, *wvl, *woh, *wol, *w1h, *w1l, *w2h, *w2l;
    bf16 *ho1h, *ho1l, *ho2h, *ho2l, *he1h, *he1l;

    cudaGetSymbolAddress((void**)&x,  g_x);   cudaGetSymbolAddress((void**)&hf, g_hf);
    cudaGetSymbolAddress((void**)&q,  g_q);   cudaGetSymbolAddress((void**)&k,  g_k);
    cudaGetSymbolAddress((void**)&v,  g_v);
    cudaGetSymbolAddress((void**)&hh, g_hh);  cudaGetSymbolAddress((void**)&hl, g_hl);
    cudaGetSymbolAddress((void**)&oh, g_oh);  cudaGetSymbolAddress((void**)&ol, g_ol);
    cudaGetSymbolAddress((void**)&mh, g_mh);  cudaGetSymbolAddress((void**)&ml, g_ml);
    cudaGetSymbolAddress((void**)&xoh, g_xoh); cudaGetSymbolAddress((void**)&xol, g_xol);
    cudaGetSymbolAddress((void**)&t1h, g_t1h); cudaGetSymbolAddress((void**)&t1l, g_t1l);
    cudaGetSymbolAddress((void**)&xeh, g_xeh); cudaGetSymbolAddress((void**)&xel, g_xel);
    cudaGetSymbolAddress((void**)&t2h, g_t2h); cudaGetSymbolAddress((void**)&t2l, g_t2l);
    cudaGetSymbolAddress((void**)&wqh, g_wqh); cudaGetSymbolAddress((void**)&wql, g_wql);
    cudaGetSymbolAddress((void**)&wkh, g_wkh); cudaGetSymbolAddress((void**)&wkl, g_wkl);
    cudaGetSymbolAddress((void**)&wvh, g_wvh); cudaGetSymbolAddress((void**)&wvl, g_wvl);
    cudaGetSymbolAddress((void**)&woh, g_woh); cudaGetSymbolAddress((void**)&wol, g_wol);
    cudaGetSymbolAddress((void**)&w1h, g_w1h); cudaGetSymbolAddress((void**)&w1l, g_w1l);
    cudaGetSymbolAddress((void**)&w2h, g_w2h); cudaGetSymbolAddress((void**)&w2l, g_w2l);
    cudaGetSymbolAddress((void**)&ho1h, g_ho1h); cudaGetSymbolAddress((void**)&ho1l, g_ho1l);
    cudaGetSymbolAddress((void**)&ho2h, g_ho2h); cudaGetSymbolAddress((void**)&ho2l, g_ho2l);
    cudaGetSymbolAddress((void**)&he1h, g_he1h); cudaGetSymbolAddress((void**)&he1l, g_he1l);

    // Split all weights to (hi,lo) bf16
    run_split(wq, wqh, wql, (size_t)L_ * D_ * D_);
    run_split(wk, wkh, wkl, (size_t)L_ * D_ * D_);
    run_split(wv, wvh, wvl, (size_t)L_ * D_ * D_);
    run_split(wo, woh, wol, (size_t)L_ * D_ * D_);
    run_split(w1, w1h, w1l, (size_t)L_ * D_ * D4_);
    run_split(w2, w2h, w2l, (size_t)L_ * D4_ * D_);
    run_split(ho1, ho1h, ho1l, (size_t)D_ * D_);
    run_split(ho2, ho2h, ho2l, (size_t)D_ * VOBS_);
    run_split(he1, he1h, he1l, (size_t)D_ * D_);

    // Embedding
    embed_kernel<<<BS_, 256>>>(tokens, pos_emb, emb_obs, emb_act, x);

    const size_t dd = (size_t)D_ * D_;
    const size_t d4 = (size_t)D_ * D4_;
    for (int i = 0; i < L_; i++) {
        ln_kernel<true><<<BS_, 256>>>(x, ln1_g + i * D_, ln1_b + i * D_, nullptr, hh, hl);
        launch_gemm3<0, false, true, false>(hh, hl, wqh + i * dd, wql + i * dd,
                                            bq + i * D_, nullptr, q, nullptr, nullptr, BS_, D_, D_);
        launch_gemm3<0, false, true, false>(hh, hl, wkh + i * dd, wkl + i * dd,
                                            bk + i * D_, nullptr, k, nullptr, nullptr, BS_, D_, D_);
        launch_gemm3<0, false, true, false>(hh, hl, wvh + i * dd, wvl + i * dd,
                                            bv + i * D_, nullptr, v, nullptr, nullptr, BS_, D_, D_);
        attn_kernel<<<dim3(16, H_, B_), 64>>>(q, k, v, oh, ol);
        launch_gemm3<0, true, true, false>(oh, ol, woh + i * dd, wol + i * dd,
                                           bo + i * D_, x, x, nullptr, nullptr, BS_, D_, D_);
        ln_kernel<true><<<BS_, 256>>>(x, ln2_g + i * D_, ln2_b + i * D_, nullptr, hh, hl);
        launch_gemm3<1, false, false, true>(hh, hl, w1h + i * d4, w1l + i * d4,
                                            b1 + i * D4_, nullptr, nullptr, mh, ml, BS_, D4_, D_);
        launch_gemm3<0, true, true, false>(mh, ml, w2h + i * d4, w2l + i * d4,
                                           b2 + i * D_, x, x, nullptr, nullptr, BS_, D_, D4_);
    }

    // Final LN + heads
    ln_kernel<false><<<BS_, 256>>>(x, lnf_g, lnf_b, hf, nullptr, nullptr);
    gather_obs_kernel<<<B_ * NOBS_, 256>>>(hf, xoh, xol);
    gather_act_kernel<<<B_ * NACT_, 256>>>(hf, xeh, xel);

    launch_gemm3<2, false, false, true>(xoh, xol, ho1h, ho1l, bo1, nullptr,
                                        nullptr, t1h, t1l, B_ * NOBS_, D_, D_);
    launch_gemm3<0, false, true, false>(t1h, t1l, ho2h, ho2l, bo2, nullptr,
                                        out, nullptr, nullptr, B_ * NOBS_, VOBS_, D_);
    launch_gemm3<2, false, false, true>(xeh, xel, he1h, he1l, be1, nullptr,
                                        nullptr, t2h, t2l, B_ * NACT_, D_, D_);
    ends_kernel<<<B_ * NACT_, 256>>>(t2h, t2l, he2, be2, out + (size_t)B_ * NOBS_ * VOBS_);
}